// round 1
// baseline (speedup 1.0000x reference)
#include <cuda_runtime.h>

// DynamicWeights: out[n,c,h,w] = relu( sum_{di,dj} qpad[n,c,h+di,w+dj] * df[n,h*W+w,3*di+dj] )
// plus zeros for the second output (shape of dynamic_filter), concatenated after out1.

#define NN 8
#define CC 640
#define HH 48
#define WW 48
#define KK 9
#define WQ (WW / 4)   // 12 float4 quads per row
#define CY 32         // channels per block

__global__ __launch_bounds__(WQ * CY) void dyn_conv_kernel(
    const float* __restrict__ q,
    const float* __restrict__ df,
    float* __restrict__ out)
{
    __shared__ float fs[KK][WW];  // filter row transposed: [k][w], each row 192B (16B aligned)

    const int h  = blockIdx.x;            // 0..47
    const int c0 = blockIdx.y * CY;       // channel chunk base
    const int n  = blockIdx.z;            // 0..7

    const int tx  = threadIdx.x;          // 0..11 (w-quad)
    const int ty  = threadIdx.y;          // 0..31 (channel)
    const int tid = ty * WQ + tx;         // 0..383

    // Cooperatively load the filter row for (n, h): 48*9 = 432 floats, transpose to [k][w].
    const float* dfr = df + ((size_t)(n * HH + h) * WW) * KK;
    for (int i = tid; i < WW * KK; i += WQ * CY) {
        int w = i / KK;
        int k = i - w * KK;
        fs[k][w] = dfr[i];
    }
    __syncthreads();

    const int c  = c0 + ty;
    const int w4 = tx * 4;
    const float* qb = q + ((size_t)(n * CC + c) * HH) * WW;

    // Load 3 rows x 6 columns of query (zero-padded at image borders).
    float r[3][6];
#pragma unroll
    for (int di = 0; di < 3; di++) {
        const int hh = h + di - 1;
        if (hh < 0 || hh >= HH) {
#pragma unroll
            for (int j = 0; j < 6; j++) r[di][j] = 0.0f;
        } else {
            const float* row = qb + hh * WW;
            float4 v = *reinterpret_cast<const float4*>(row + w4);  // aligned: w4 % 4 == 0
            r[di][1] = v.x; r[di][2] = v.y; r[di][3] = v.z; r[di][4] = v.w;
            r[di][0] = (w4 > 0)       ? __ldg(row + w4 - 1) : 0.0f;
            r[di][5] = (w4 + 4 < WW)  ? __ldg(row + w4 + 4) : 0.0f;
        }
    }

    float acc0 = 0.f, acc1 = 0.f, acc2 = 0.f, acc3 = 0.f;
#pragma unroll
    for (int di = 0; di < 3; di++) {
#pragma unroll
        for (int dj = 0; dj < 3; dj++) {
            const int k = di * 3 + dj;
            // filter values for the 4 outputs: fs[k][w4 .. w4+3], aligned float4
            float4 f = *reinterpret_cast<const float4*>(&fs[k][w4]);
            acc0 = fmaf(r[di][dj + 0], f.x, acc0);
            acc1 = fmaf(r[di][dj + 1], f.y, acc1);
            acc2 = fmaf(r[di][dj + 2], f.z, acc2);
            acc3 = fmaf(r[di][dj + 3], f.w, acc3);
        }
    }

    float4 o;
    o.x = fmaxf(acc0, 0.0f);
    o.y = fmaxf(acc1, 0.0f);
    o.z = fmaxf(acc2, 0.0f);
    o.w = fmaxf(acc3, 0.0f);

    float* orow = out + ((size_t)(n * CC + c) * HH + h) * WW + w4;
    *reinterpret_cast<float4*>(orow) = o;
}

__global__ void zero_tail_kernel(float4* __restrict__ p, int n4)
{
    int i = blockIdx.x * blockDim.x + threadIdx.x;
    if (i < n4) p[i] = make_float4(0.f, 0.f, 0.f, 0.f);
}

extern "C" void kernel_launch(void* const* d_in, const int* in_sizes, int n_in,
                              void* d_out, int out_size)
{
    const float* q  = (const float*)d_in[0];
    const float* df = (const float*)d_in[1];
    // Defensive: if input order is swapped, detect by element count.
    const int q_elems = NN * CC * HH * WW;         // 11,796,480
    if (n_in >= 2 && in_sizes[0] != q_elems) {
        const float* t = q; q = df; df = t;
    }

    float* out = (float*)d_out;

    dim3 blk(WQ, CY);                 // 12 x 32 = 384 threads
    dim3 grd(HH, CC / CY, NN);        // 48 x 20 x 8 = 7680 blocks
    dyn_conv_kernel<<<grd, blk>>>(q, df, out);

    // Second output (zeros, shape of dynamic_filter) appended after out1 — only if
    // the harness allocated room for it.
    const int tail = out_size - q_elems;           // expected 8*48*48*9 = 165,888
    if (tail > 0) {
        int n4 = tail / 4;                         // 165888 % 4 == 0
        int threads = 256;
        int blocks = (n4 + threads - 1) / threads;
        zero_tail_kernel<<<blocks, threads>>>(
            reinterpret_cast<float4*>(out + q_elems), n4);
    }
}

// round 2
// speedup vs baseline: 1.1451x; 1.1451x over previous
#include <cuda_runtime.h>

// out[n,c,h,w] = relu( sum_{di,dj} qpad[n,c,h+di,w+dj] * df[n,(h*W+w),3*di+dj] )
// followed by a zeroed tail of shape dynamic_filter. Single fused kernel.

#define NN 8
#define CC 640
#define HH 48
#define WW 48
#define KK 9
#define HT 4                 // output rows per thread (rolling 3-row window)
#define WQ (WW / 4)          // 12 float4 quads per row
#define CY 32                // channels per block
#define THREADS (WQ * CY)    // 384

__global__ __launch_bounds__(THREADS) void dyn_conv_fused_kernel(
    const float* __restrict__ q,
    const float* __restrict__ df,
    float* __restrict__ out,
    int tail_n4)             // number of float4s to zero after out1 (0 if none)
{
    // ---- tail-zero slice: blockIdx.y == CC/CY ----
    if (blockIdx.y == CC / CY) {
        const int q_elems = NN * CC * HH * WW;
        float4* p = reinterpret_cast<float4*>(out + q_elems);
        const int tid    = threadIdx.y * WQ + threadIdx.x;
        const int gtid   = (blockIdx.z * gridDim.x + blockIdx.x) * THREADS + tid;
        const int stride = gridDim.x * gridDim.z * THREADS;   // 12*8*384 = 36864
        for (int i = gtid; i < tail_n4; i += stride)
            p[i] = make_float4(0.f, 0.f, 0.f, 0.f);
        return;
    }

    __shared__ float fs[HT][KK][WW];   // filter rows transposed: [h][k][w]

    const int h0 = blockIdx.x * HT;        // 0,4,...,44
    const int c0 = blockIdx.y * CY;
    const int n  = blockIdx.z;

    const int tx  = threadIdx.x;           // 0..11
    const int ty  = threadIdx.y;           // 0..31
    const int tid = ty * WQ + tx;

    // Cooperative filter load: HT*W*K = 1728 contiguous floats, transposed into smem.
    {
        const float* dfr = df + (size_t)(n * HH + h0) * WW * KK;
#pragma unroll
        for (int it = 0; it < (HT * WW * KK + THREADS - 1) / THREADS; it++) {
            int i = tid + it * THREADS;
            if (i < HT * WW * KK) {
                int hi  = i / (WW * KK);
                int rem = i - hi * (WW * KK);
                int w   = rem / KK;
                int k   = rem - w * KK;
                fs[hi][k][w] = dfr[i];
            }
        }
    }
    __syncthreads();

    const int c  = c0 + ty;
    const int w4 = tx * 4;
    const float* qb = q + ((size_t)(n * CC + c) * HH) * WW;
    float* ob       = out + (((size_t)(n * CC + c) * HH) + h0) * WW + w4;

    // rolling 3-row window; rows[s][0..5] covers w4-1 .. w4+4 (zero-padded)
    float rows[3][6];

    auto load_row = [&](float r[6], int hh) {
        if (hh < 0 || hh >= HH) {
#pragma unroll
            for (int j = 0; j < 6; j++) r[j] = 0.0f;
        } else {
            const float* row = qb + hh * WW;
            float4 v = *reinterpret_cast<const float4*>(row + w4);  // 16B aligned
            r[1] = v.x; r[2] = v.y; r[3] = v.z; r[4] = v.w;
            r[0] = (w4 > 0)      ? row[w4 - 1] : 0.0f;
            r[5] = (w4 + 4 < WW) ? row[w4 + 4] : 0.0f;
        }
    };

    load_row(rows[0], h0 - 1);
    load_row(rows[1], h0);

#pragma unroll
    for (int i = 0; i < HT; i++) {
        load_row(rows[(i + 2) % 3], h0 + i + 1);

        float acc0 = 0.f, acc1 = 0.f, acc2 = 0.f, acc3 = 0.f;
#pragma unroll
        for (int di = 0; di < 3; di++) {
            const float* rr = rows[(i + di) % 3];   // constant index after unroll
#pragma unroll
            for (int dj = 0; dj < 3; dj++) {
                const int k = di * 3 + dj;
                float4 f = *reinterpret_cast<const float4*>(&fs[i][k][w4]);  // 16B aligned
                acc0 = fmaf(rr[dj + 0], f.x, acc0);
                acc1 = fmaf(rr[dj + 1], f.y, acc1);
                acc2 = fmaf(rr[dj + 2], f.z, acc2);
                acc3 = fmaf(rr[dj + 3], f.w, acc3);
            }
        }

        float4 o;
        o.x = fmaxf(acc0, 0.0f);
        o.y = fmaxf(acc1, 0.0f);
        o.z = fmaxf(acc2, 0.0f);
        o.w = fmaxf(acc3, 0.0f);
        *reinterpret_cast<float4*>(ob + i * WW) = o;
    }
}

extern "C" void kernel_launch(void* const* d_in, const int* in_sizes, int n_in,
                              void* d_out, int out_size)
{
    const float* q  = (const float*)d_in[0];
    const float* df = (const float*)d_in[1];
    const int q_elems = NN * CC * HH * WW;   // 11,796,480
    if (n_in >= 2 && in_sizes[0] != q_elems) {
        const float* t = q; q = df; df = t;  // defensive input-order swap
    }

    float* out = (float*)d_out;

    const int tail = out_size - q_elems;     // expected 165,888
    const int tail_n4 = (tail > 0) ? tail / 4 : 0;

    dim3 blk(WQ, CY);                                        // 384 threads
    dim3 grd(HH / HT, CC / CY + (tail_n4 > 0 ? 1 : 0), NN);  // 12 x 21 x 8
    dyn_conv_fused_kernel<<<grd, blk>>>(q, df, out, tail_n4);
}

// round 4
// speedup vs baseline: 1.6015x; 1.3985x over previous
#include <cuda_runtime.h>

#define NN 8
#define CC 640
#define HH 48
#define WW 48
#define KK 9
#define HT 4                  // output rows per thread (rolling 3-row window)
#define WQ 12                 // w-quads per row (48/4)
#define TY 16
#define THREADS (WQ * TY)     // 192
#define CB 2                  // channels per thread
#define CBLK (TY * CB)        // 32 channels per block

__global__ __launch_bounds__(THREADS) void dyn_conv_kernel(
    const float* __restrict__ q,
    const float* __restrict__ df,
    float* __restrict__ out,
    int tail_n4)
{
    // ---- fused tail-zero slice ----
    if (blockIdx.y == CC / CBLK) {
        const int q_elems = NN * CC * HH * WW;
        float4* p = reinterpret_cast<float4*>(out + q_elems);
        const int tid    = threadIdx.y * WQ + threadIdx.x;
        const int gtid   = (blockIdx.z * gridDim.x + blockIdx.x) * THREADS + tid;
        const int stride = gridDim.x * gridDim.z * THREADS;
        for (int i = gtid; i < tail_n4; i += stride)
            p[i] = make_float4(0.f, 0.f, 0.f, 0.f);
        return;
    }

    __shared__ float fs[HT][KK][WW];   // filter transposed: [h][k][w]

    const int h0 = blockIdx.x * HT;
    const int c0 = blockIdx.y * CBLK;
    const int n  = blockIdx.z;

    const int tx  = threadIdx.x;       // 0..11
    const int ty  = threadIdx.y;       // 0..15
    const int tid = ty * WQ + tx;

    // Cooperative filter load: HT*W*K = 1728 floats; 1728/192 = 9 iterations.
    {
        const float* dfr = df + (size_t)(n * HH + h0) * WW * KK;
#pragma unroll
        for (int it = 0; it < (HT * WW * KK) / THREADS; it++) {
            int i   = tid + it * THREADS;
            int hi  = i / (WW * KK);
            int rem = i - hi * (WW * KK);
            int w   = rem / KK;
            int k   = rem - w * KK;
            fs[hi][k][w] = dfr[i];
        }
    }
    __syncthreads();

    const int w4 = tx * 4;

    const float* qb[CB];
    float*       ob[CB];
#pragma unroll
    for (int cb = 0; cb < CB; cb++) {
        const int c = c0 + ty + cb * TY;
        qb[cb] = q   + ((size_t)(n * CC + c) * HH) * WW;
        ob[cb] = out + (((size_t)(n * CC + c) * HH) + h0) * WW + w4;
    }

    // rolling 3-row window per channel; [0..5] covers w4-1 .. w4+4 (zero-padded)
    float rows[CB][3][6];

    auto load_rows = [&](int s, int hh) {
        const bool ok = (hh >= 0) && (hh < HH);
#pragma unroll
        for (int cb = 0; cb < CB; cb++) {
            float* r = rows[cb][s];
            if (!ok) {
#pragma unroll
                for (int j = 0; j < 6; j++) r[j] = 0.0f;
            } else {
                const float* row = qb[cb] + hh * WW;
                float4 v = *reinterpret_cast<const float4*>(row + w4);  // 16B aligned
                r[1] = v.x; r[2] = v.y; r[3] = v.z; r[4] = v.w;
                r[0] = (w4 > 0)      ? row[w4 - 1] : 0.0f;
                r[5] = (w4 + 4 < WW) ? row[w4 + 4] : 0.0f;
            }
        }
    };

    load_rows(0, h0 - 1);
    load_rows(1, h0);

#pragma unroll
    for (int i = 0; i < HT; i++) {
        load_rows((i + 2) % 3, h0 + i + 1);

        // Filter for this output row: 9 float4s, loaded ONCE, reused for CB channels.
        float4 f[KK];
#pragma unroll
        for (int k = 0; k < KK; k++)
            f[k] = *reinterpret_cast<const float4*>(&fs[i][k][w4]);

#pragma unroll
        for (int cb = 0; cb < CB; cb++) {
            float acc0 = 0.f, acc1 = 0.f, acc2 = 0.f, acc3 = 0.f;
#pragma unroll
            for (int di = 0; di < 3; di++) {
                const float* rr = rows[cb][(i + di) % 3];  // constant after unroll
#pragma unroll
                for (int dj = 0; dj < 3; dj++) {
                    const int k = di * 3 + dj;
                    acc0 = fmaf(rr[dj + 0], f[k].x, acc0);
                    acc1 = fmaf(rr[dj + 1], f[k].y, acc1);
                    acc2 = fmaf(rr[dj + 2], f[k].z, acc2);
                    acc3 = fmaf(rr[dj + 3], f[k].w, acc3);
                }
            }
            float4 o;
            o.x = fmaxf(acc0, 0.0f);
            o.y = fmaxf(acc1, 0.0f);
            o.z = fmaxf(acc2, 0.0f);
            o.w = fmaxf(acc3, 0.0f);
            *reinterpret_cast<float4*>(ob[cb] + i * WW) = o;
        }
    }
}

extern "C" void kernel_launch(void* const* d_in, const int* in_sizes, int n_in,
                              void* d_out, int out_size)
{
    const float* q  = (const float*)d_in[0];
    const float* df = (const float*)d_in[1];
    const int q_elems = NN * CC * HH * WW;
    if (n_in >= 2 && in_sizes[0] != q_elems) {
        const float* t = q; q = df; df = t;
    }

    float* out = (float*)d_out;

    const int tail    = out_size - q_elems;
    const int tail_n4 = (tail > 0) ? tail / 4 : 0;

    dim3 blk(WQ, TY);                                          // 192 threads
    dim3 grd(HH / HT, CC / CBLK + (tail_n4 > 0 ? 1 : 0), NN);  // 12 x 21 x 8
    dyn_conv_kernel<<<grd, blk>>>(q, df, out, tail_n4);
}